// round 2
// baseline (speedup 1.0000x reference)
#include <cuda_runtime.h>
#include <cuda_fp16.h>
#include <cstdint>

// ---------------------------------------------------------------------------
// GPe masked GEMM: out[b,u] = sum_i inputs[b,i]*(w[i,u]*mask[u,i]) + bias[u]
//   inputs [16384,3072] f32, w [3072,3072] f32, bias [3072] f32,
//   mask [3072,3072] i32 ([units, in]).
// Build target is compute_103 (no 'a') -> NO tcgen05/TMA. Use legacy
// mma.sync.m16n8k16 (fp16 in, f32 accum) with cp.async multistage pipeline.
// fp16 precision ~= tf32 (11-bit mantissa): output rel err ~2.5e-4 < 1e-3.
// w scaled by 2^14 in prep (avoids fp16 denormals), epilogue scales by 2^-14.
// ---------------------------------------------------------------------------

#define DB 16384
#define DK 3072
#define DN 3072
#define BM 128
#define BN 128
#define BK 32
#define NKI (DK / BK)          /* 96 */
#define NSTG 4
#define A_STAGE_BYTES (BM * BK * 2)    /* 8192  */
#define B_STAGE_BYTES (BN * BK * 2)    /* 8192  */
#define STAGE_BYTES (A_STAGE_BYTES + B_STAGE_BYTES)  /* 16384 */
#define SMEM_BYTES (NSTG * STAGE_BYTES)              /* 65536 */

#define W_SCALE 16384.0f
#define W_INV   (1.0f / 16384.0f)

__device__ __align__(128) __half g_Ah[(size_t)DB * DK];  // fp16 inputs
__device__ __align__(128) __half g_Wh[(size_t)DN * DK];  // fp16 (w*mask*2^14)^T, [N,K] k-major

// ------------------------------- helpers -----------------------------------

__device__ __forceinline__ void cp16(uint32_t d, const void* s) {
    asm volatile("cp.async.cg.shared.global [%0], [%1], 16;" :: "r"(d), "l"(s) : "memory");
}
__device__ __forceinline__ void cp_commit() { asm volatile("cp.async.commit_group;" ::: "memory"); }
template <int N>
__device__ __forceinline__ void cp_wait() { asm volatile("cp.async.wait_group %0;" :: "n"(N) : "memory"); }

__device__ __forceinline__ void mma_f16(float& d0, float& d1, float& d2, float& d3,
                                        uint32_t a0, uint32_t a1, uint32_t a2, uint32_t a3,
                                        uint32_t b0, uint32_t b1) {
    asm volatile("mma.sync.aligned.m16n8k16.row.col.f32.f16.f16.f32 "
                 "{%0,%1,%2,%3}, {%4,%5,%6,%7}, {%8,%9}, {%0,%1,%2,%3};"
                 : "+f"(d0), "+f"(d1), "+f"(d2), "+f"(d3)
                 : "r"(a0), "r"(a1), "r"(a2), "r"(a3), "r"(b0), "r"(b1));
}

// --------------------------- prep kernels ----------------------------------

__global__ void prep_a_kernel(const float4* __restrict__ in) {
    size_t i = (size_t)blockIdx.x * blockDim.x + threadIdx.x;
    const size_t stride = (size_t)gridDim.x * blockDim.x;
    uint2* o = reinterpret_cast<uint2*>(g_Ah);
    const size_t n4 = (size_t)DB * DK / 4;
    for (; i < n4; i += stride) {
        float4 v = __ldg(in + i);
        __half2 h01 = __floats2half2_rn(v.x, v.y);
        __half2 h23 = __floats2half2_rn(v.z, v.w);
        uint2 u;
        u.x = *reinterpret_cast<uint32_t*>(&h01);
        u.y = *reinterpret_cast<uint32_t*>(&h23);
        o[i] = u;
    }
}

// g_Wh[n][k] = half(w[k][n] * mask[n][k] * 2^14), 32x32 smem transpose tiles.
__global__ void prep_w_kernel(const float* __restrict__ w, const int* __restrict__ mask) {
    __shared__ float t[32][33];
    const int k0 = blockIdx.x * 32, n0 = blockIdx.y * 32;
    const int tx = threadIdx.x, ty = threadIdx.y;   // (32, 8)
#pragma unroll
    for (int j = 0; j < 4; ++j) {
        int k = k0 + ty + 8 * j;
        t[ty + 8 * j][tx] = w[(size_t)k * DN + n0 + tx];
    }
    __syncthreads();
#pragma unroll
    for (int j = 0; j < 4; ++j) {
        int n = n0 + ty + 8 * j;
        int k = k0 + tx;
        float v = t[tx][ty + 8 * j] * (float)mask[(size_t)n * DK + k] * W_SCALE;
        g_Wh[(size_t)n * DK + k] = __float2half_rn(v);
    }
}

// ------------------------------ GEMM ---------------------------------------
// 128x128x32 CTA tile, 256 threads = 8 warps (2 m x 4 n), warp tile 64x32.
// Smem per stage: A[128][32] fp16 (row-major, 64B rows, xor-swizzled 16B
// chunks: chunk' = chunk ^ ((row>>1)&3)), B same layout ([n][k] k-major).

__global__ void __launch_bounds__(256) gemm_f16(const float* __restrict__ bias,
                                                float* __restrict__ out) {
    extern __shared__ char smem[];

    const int tid = threadIdx.x;
    const int wid = tid >> 5;
    const int lane = tid & 31;
    const int gid = lane >> 2;      // 0..7
    const int tg = lane & 3;        // 0..3
    const int warp_m = wid & 1;     // 0..1
    const int warp_n = wid >> 1;    // 0..3
    const int m0 = blockIdx.y * BM;
    const int n0 = blockIdx.x * BN;

    // ---- cp.async source/dest precompute (2 A chunks + 2 B chunks/thread) --
    uint32_t aDst[2], bDst[2];
    const __half* aSrc[2];
    const __half* bSrc[2];
    {
        const __half* gA = g_Ah + (size_t)m0 * DK;
        const __half* gW = g_Wh + (size_t)n0 * DK;
#pragma unroll
        for (int j = 0; j < 2; ++j) {
            int cid = tid + 256 * j;            // 0..511
            int row = cid >> 2;                 // 0..127
            int c4 = cid & 3;                   // 16B chunk within 64B row
            uint32_t sm = (uint32_t)row * 64u + (uint32_t)((c4 ^ ((row >> 1) & 3)) * 16);
            aDst[j] = sm;                       // A at stage offset 0
            bDst[j] = sm + A_STAGE_BYTES;       // B at stage offset 8192
            aSrc[j] = gA + (size_t)row * DK + c4 * 8;   // 8 halves = 16B
            bSrc[j] = gW + (size_t)row * DK + c4 * 8;
        }
    }
    const uint32_t smemBase = (uint32_t)__cvta_generic_to_shared(smem);

    // ---- fragment smem offsets (stage-relative) ----------------------------
    const int sw = (gid >> 1) & 3;              // xor-swizzle key, same for A & B
    uint32_t aOff[4], bOff[4];
#pragma unroll
    for (int mi = 0; mi < 4; ++mi)
        aOff[mi] = (uint32_t)(warp_m * 64 + mi * 16 + gid) * 64u;
#pragma unroll
    for (int ni = 0; ni < 4; ++ni)
        bOff[ni] = A_STAGE_BYTES + (uint32_t)(warp_n * 32 + ni * 8 + gid) * 64u;

    float acc[4][4][4];
#pragma unroll
    for (int mi = 0; mi < 4; ++mi)
#pragma unroll
        for (int ni = 0; ni < 4; ++ni)
#pragma unroll
            for (int q = 0; q < 4; ++q) acc[mi][ni][q] = 0.0f;

    // ---- prologue: fill stages 0..NSTG-2 -----------------------------------
#pragma unroll
    for (int p = 0; p < NSTG - 1; ++p) {
        uint32_t st = smemBase + p * STAGE_BYTES;
        size_t kofs = (size_t)p * BK;
#pragma unroll
        for (int j = 0; j < 2; ++j) cp16(st + aDst[j], aSrc[j] + kofs);
#pragma unroll
        for (int j = 0; j < 2; ++j) cp16(st + bDst[j], bSrc[j] + kofs);
        cp_commit();
    }

    // ---- mainloop ----------------------------------------------------------
    for (int it = 0; it < NKI; ++it) {
        cp_wait<NSTG - 2>();
        __syncthreads();

        // issue loads for iteration it+NSTG-1
        int nf = it + NSTG - 1;
        if (nf < NKI) {
            uint32_t st = smemBase + (nf & (NSTG - 1)) * STAGE_BYTES;
            size_t kofs = (size_t)nf * BK;
#pragma unroll
            for (int j = 0; j < 2; ++j) cp16(st + aDst[j], aSrc[j] + kofs);
#pragma unroll
            for (int j = 0; j < 2; ++j) cp16(st + bDst[j], bSrc[j] + kofs);
        }
        cp_commit();

        // compute on stage it
        const char* stg = smem + (it & (NSTG - 1)) * STAGE_BYTES;
#pragma unroll
        for (int ks = 0; ks < 2; ++ks) {
            const uint32_t cb0 = (uint32_t)(((2 * ks) ^ sw) << 4) + 4 * tg;
            const uint32_t cb1 = (uint32_t)(((2 * ks + 1) ^ sw) << 4) + 4 * tg;

            uint32_t af[4][4];
#pragma unroll
            for (int mi = 0; mi < 4; ++mi) {
                af[mi][0] = *reinterpret_cast<const uint32_t*>(stg + aOff[mi] + cb0);
                af[mi][1] = *reinterpret_cast<const uint32_t*>(stg + aOff[mi] + 512 + cb0);
                af[mi][2] = *reinterpret_cast<const uint32_t*>(stg + aOff[mi] + cb1);
                af[mi][3] = *reinterpret_cast<const uint32_t*>(stg + aOff[mi] + 512 + cb1);
            }
            uint32_t bf[4][2];
#pragma unroll
            for (int ni = 0; ni < 4; ++ni) {
                bf[ni][0] = *reinterpret_cast<const uint32_t*>(stg + bOff[ni] + cb0);
                bf[ni][1] = *reinterpret_cast<const uint32_t*>(stg + bOff[ni] + cb1);
            }
#pragma unroll
            for (int mi = 0; mi < 4; ++mi)
#pragma unroll
                for (int ni = 0; ni < 4; ++ni)
                    mma_f16(acc[mi][ni][0], acc[mi][ni][1], acc[mi][ni][2], acc[mi][ni][3],
                            af[mi][0], af[mi][1], af[mi][2], af[mi][3],
                            bf[ni][0], bf[ni][1]);
        }
    }
    cp_wait<0>();   // drain before exit

    // ---- epilogue: scale by 2^-14, add bias, direct float2 stores ----------
#pragma unroll
    for (int mi = 0; mi < 4; ++mi) {
        const int row0 = m0 + warp_m * 64 + mi * 16 + gid;
#pragma unroll
        for (int ni = 0; ni < 4; ++ni) {
            const int col = n0 + warp_n * 32 + ni * 8 + 2 * tg;
            const float2 bb = *reinterpret_cast<const float2*>(bias + col);
            float2 v0, v1;
            v0.x = acc[mi][ni][0] * W_INV + bb.x;
            v0.y = acc[mi][ni][1] * W_INV + bb.y;
            v1.x = acc[mi][ni][2] * W_INV + bb.x;
            v1.y = acc[mi][ni][3] * W_INV + bb.y;
            *reinterpret_cast<float2*>(out + (size_t)row0 * DN + col) = v0;
            *reinterpret_cast<float2*>(out + (size_t)(row0 + 8) * DN + col) = v1;
        }
    }
}

// ------------------------------ launch -------------------------------------

extern "C" void kernel_launch(void* const* d_in, const int* in_sizes, int n_in,
                              void* d_out, int out_size) {
    (void)in_sizes; (void)n_in; (void)out_size;
    const float* inp  = (const float*)d_in[0];
    const float* w    = (const float*)d_in[1];
    const float* bias = (const float*)d_in[2];
    const int*   mask = (const int*)d_in[3];
    float* out = (float*)d_out;

    static bool attr_set = false;
    if (!attr_set) {
        cudaFuncSetAttribute(gemm_f16, cudaFuncAttributeMaxDynamicSharedMemorySize, SMEM_BYTES);
        attr_set = true;
    }

    prep_a_kernel<<<4096, 256>>>((const float4*)inp);
    prep_w_kernel<<<dim3(DK / 32, DN / 32), dim3(32, 8)>>>(w, mask);
    gemm_f16<<<dim3(DN / BN, DB / BM), 256, SMEM_BYTES>>>(bias, out);
}

// round 3
// speedup vs baseline: 1.1990x; 1.1990x over previous
#include <cuda_runtime.h>
#include <cuda_fp16.h>
#include <cstdint>

// ---------------------------------------------------------------------------
// GPe masked GEMM: out[b,u] = sum_i inputs[b,i]*(w[i,u]*mask[u,i]) + bias[u]
// compute_103 (no 'a') -> legacy mma.sync.m16n8k16 fp16/f32acc path.
// R3: ldmatrix.x4 fragment loads + 128x256x32 CTA tile (warp tile 64x64),
// 4-stage cp.async pipeline, 256 threads (8 warps, 2m x 4n).
// ---------------------------------------------------------------------------

#define DB 16384
#define DK 3072
#define DN 3072
#define BM 128
#define BN 256
#define BK 32
#define NKI (DK / BK)          /* 96 */
#define NSTG 4
#define A_STAGE_BYTES (BM * BK * 2)    /* 8192  */
#define B_STAGE_BYTES (BN * BK * 2)    /* 16384 */
#define STAGE_BYTES (A_STAGE_BYTES + B_STAGE_BYTES)  /* 24576 */
#define SMEM_BYTES (NSTG * STAGE_BYTES)              /* 98304 */

#define W_SCALE 16384.0f
#define W_INV   (1.0f / 16384.0f)

__device__ __align__(128) __half g_Ah[(size_t)DB * DK];  // fp16 inputs
__device__ __align__(128) __half g_Wh[(size_t)DN * DK];  // fp16 (w*mask*2^14)^T, [N,K]

// ------------------------------- helpers -----------------------------------

__device__ __forceinline__ void cp16(uint32_t d, const void* s) {
    asm volatile("cp.async.cg.shared.global [%0], [%1], 16;" :: "r"(d), "l"(s) : "memory");
}
__device__ __forceinline__ void cp_commit() { asm volatile("cp.async.commit_group;" ::: "memory"); }
template <int N>
__device__ __forceinline__ void cp_wait() { asm volatile("cp.async.wait_group %0;" :: "n"(N) : "memory"); }

__device__ __forceinline__ void ldsm4(uint32_t& r0, uint32_t& r1, uint32_t& r2, uint32_t& r3,
                                      uint32_t addr) {
    asm volatile("ldmatrix.sync.aligned.m8n8.x4.shared.b16 {%0,%1,%2,%3}, [%4];"
                 : "=r"(r0), "=r"(r1), "=r"(r2), "=r"(r3) : "r"(addr));
}

__device__ __forceinline__ void mma_f16(float& d0, float& d1, float& d2, float& d3,
                                        uint32_t a0, uint32_t a1, uint32_t a2, uint32_t a3,
                                        uint32_t b0, uint32_t b1) {
    asm volatile("mma.sync.aligned.m16n8k16.row.col.f32.f16.f16.f32 "
                 "{%0,%1,%2,%3}, {%4,%5,%6,%7}, {%8,%9}, {%0,%1,%2,%3};"
                 : "+f"(d0), "+f"(d1), "+f"(d2), "+f"(d3)
                 : "r"(a0), "r"(a1), "r"(a2), "r"(a3), "r"(b0), "r"(b1));
}

// --------------------------- prep kernels ----------------------------------

__global__ void prep_a_kernel(const float4* __restrict__ in) {
    size_t i = (size_t)blockIdx.x * blockDim.x + threadIdx.x;
    const size_t stride = (size_t)gridDim.x * blockDim.x;
    uint2* o = reinterpret_cast<uint2*>(g_Ah);
    const size_t n4 = (size_t)DB * DK / 4;
    for (; i < n4; i += stride) {
        float4 v = __ldg(in + i);
        __half2 h01 = __floats2half2_rn(v.x, v.y);
        __half2 h23 = __floats2half2_rn(v.z, v.w);
        uint2 u;
        u.x = *reinterpret_cast<uint32_t*>(&h01);
        u.y = *reinterpret_cast<uint32_t*>(&h23);
        o[i] = u;
    }
}

// g_Wh[n][k] = half(w[k][n] * mask[n][k] * 2^14), 32x32 smem transpose tiles.
__global__ void prep_w_kernel(const float* __restrict__ w, const int* __restrict__ mask) {
    __shared__ float t[32][33];
    const int k0 = blockIdx.x * 32, n0 = blockIdx.y * 32;
    const int tx = threadIdx.x, ty = threadIdx.y;   // (32, 8)
#pragma unroll
    for (int j = 0; j < 4; ++j) {
        int k = k0 + ty + 8 * j;
        t[ty + 8 * j][tx] = w[(size_t)k * DN + n0 + tx];
    }
    __syncthreads();
#pragma unroll
    for (int j = 0; j < 4; ++j) {
        int n = n0 + ty + 8 * j;
        int k = k0 + tx;
        float v = t[tx][ty + 8 * j] * (float)mask[(size_t)n * DK + k] * W_SCALE;
        g_Wh[(size_t)n * DK + k] = __float2half_rn(v);
    }
}

// ------------------------------ GEMM ---------------------------------------
// Smem stage: A[128][32] fp16 then B[256][32] fp16, 64B rows, 16B-chunk xor
// swizzle: chunk' = chunk ^ ((row>>1)&3). Conflict-free for cp.async writes
// and ldmatrix reads.

__global__ void __launch_bounds__(256, 1) gemm_f16(const float* __restrict__ bias,
                                                   float* __restrict__ out) {
    extern __shared__ char smem[];

    const int tid = threadIdx.x;
    const int wid = tid >> 5;
    const int lane = tid & 31;
    const int gid = lane >> 2;
    const int tg = lane & 3;
    const int warp_m = wid & 1;     // 0..1 -> 64-row slice
    const int warp_n = wid >> 1;    // 0..3 -> 64-col slice
    const int m0 = blockIdx.y * BM;
    const int n0 = blockIdx.x * BN;

    const uint32_t smemBase = (uint32_t)__cvta_generic_to_shared(smem);

    // ---- cp.async src/dst: A 2 chunks + B 4 chunks per thread --------------
    uint32_t aDst[2], bDst[4];
    const __half* aSrc[2];
    const __half* bSrc[4];
    {
        const __half* gA = g_Ah + (size_t)m0 * DK;
        const __half* gW = g_Wh + (size_t)n0 * DK;
#pragma unroll
        for (int j = 0; j < 2; ++j) {
            int cid = tid + 256 * j;            // 0..511 (A: 128 rows x 4 chunks)
            int row = cid >> 2, c4 = cid & 3;
            aDst[j] = (uint32_t)row * 64u + (uint32_t)((c4 ^ ((row >> 1) & 3)) * 16);
            aSrc[j] = gA + (size_t)row * DK + c4 * 8;
        }
#pragma unroll
        for (int j = 0; j < 4; ++j) {
            int cid = tid + 256 * j;            // 0..1023 (B: 256 rows x 4 chunks)
            int row = cid >> 2, c4 = cid & 3;
            bDst[j] = A_STAGE_BYTES + (uint32_t)row * 64u + (uint32_t)((c4 ^ ((row >> 1) & 3)) * 16);
            bSrc[j] = gW + (size_t)row * DK + c4 * 8;
        }
    }

    // ---- ldmatrix addresses (stage-relative), per ks in {0,1} --------------
    uint32_t aAddr[2][4], bAddr[2][4];
    {
        // A: lanes 0-15 rows r..r+15 chunk base 0; lanes 16-31 same rows chunk 1
        const int ar = warp_m * 64 + (lane & 15);
        const int ac0 = lane >> 4;
#pragma unroll
        for (int mi = 0; mi < 4; ++mi) {
            int row = ar + mi * 16;
            int key = (row >> 1) & 3;
#pragma unroll
            for (int ks = 0; ks < 2; ++ks)
                aAddr[ks][mi] = (uint32_t)row * 64u + (uint32_t)(((ac0 + 2 * ks) ^ key) << 4);
        }
        // B: matrix id m = lane>>3; n-row = nj*16 + (m>=2)*8 + (lane&7); chunk = m&1
        const int br = warp_n * 64 + ((lane >> 4) << 3) + (lane & 7);
        const int bc0 = (lane >> 3) & 1;
#pragma unroll
        for (int nj = 0; nj < 4; ++nj) {
            int row = br + nj * 16;
            int key = (row >> 1) & 3;
#pragma unroll
            for (int ks = 0; ks < 2; ++ks)
                bAddr[ks][nj] = A_STAGE_BYTES + (uint32_t)row * 64u
                              + (uint32_t)(((bc0 + 2 * ks) ^ key) << 4);
        }
    }

    float acc[4][8][4];
#pragma unroll
    for (int mi = 0; mi < 4; ++mi)
#pragma unroll
        for (int ni = 0; ni < 8; ++ni)
#pragma unroll
            for (int q = 0; q < 4; ++q) acc[mi][ni][q] = 0.0f;

    // ---- prologue: fill stages 0..2 ----------------------------------------
#pragma unroll
    for (int p = 0; p < NSTG - 1; ++p) {
        uint32_t st = smemBase + p * STAGE_BYTES;
        size_t kofs = (size_t)p * BK;
#pragma unroll
        for (int j = 0; j < 2; ++j) cp16(st + aDst[j], aSrc[j] + kofs);
#pragma unroll
        for (int j = 0; j < 4; ++j) cp16(st + bDst[j], bSrc[j] + kofs);
        cp_commit();
    }

    // ---- mainloop ----------------------------------------------------------
    for (int it = 0; it < NKI; ++it) {
        cp_wait<NSTG - 2>();
        __syncthreads();

        const int nf = it + NSTG - 1;
        if (nf < NKI) {
            uint32_t st = smemBase + (nf & (NSTG - 1)) * STAGE_BYTES;
            size_t kofs = (size_t)nf * BK;
#pragma unroll
            for (int j = 0; j < 2; ++j) cp16(st + aDst[j], aSrc[j] + kofs);
#pragma unroll
            for (int j = 0; j < 4; ++j) cp16(st + bDst[j], bSrc[j] + kofs);
        }
        cp_commit();

        const uint32_t stg = smemBase + (it & (NSTG - 1)) * STAGE_BYTES;
#pragma unroll
        for (int ks = 0; ks < 2; ++ks) {
            uint32_t bf[4][4];
#pragma unroll
            for (int nj = 0; nj < 4; ++nj)
                ldsm4(bf[nj][0], bf[nj][1], bf[nj][2], bf[nj][3], stg + bAddr[ks][nj]);
#pragma unroll
            for (int mi = 0; mi < 4; ++mi) {
                uint32_t a0, a1, a2, a3;
                ldsm4(a0, a1, a2, a3, stg + aAddr[ks][mi]);
#pragma unroll
                for (int nj = 0; nj < 4; ++nj) {
                    mma_f16(acc[mi][2 * nj][0], acc[mi][2 * nj][1],
                            acc[mi][2 * nj][2], acc[mi][2 * nj][3],
                            a0, a1, a2, a3, bf[nj][0], bf[nj][1]);
                    mma_f16(acc[mi][2 * nj + 1][0], acc[mi][2 * nj + 1][1],
                            acc[mi][2 * nj + 1][2], acc[mi][2 * nj + 1][3],
                            a0, a1, a2, a3, bf[nj][2], bf[nj][3]);
                }
            }
        }
    }
    cp_wait<0>();

    // ---- epilogue: scale 2^-14 + bias, float2 direct stores ----------------
#pragma unroll
    for (int mi = 0; mi < 4; ++mi) {
        const int row0 = m0 + warp_m * 64 + mi * 16 + gid;
#pragma unroll
        for (int ni = 0; ni < 8; ++ni) {
            const int col = n0 + warp_n * 64 + ni * 8 + 2 * tg;
            const float2 bb = *reinterpret_cast<const float2*>(bias + col);
            float2 v0, v1;
            v0.x = acc[mi][ni][0] * W_INV + bb.x;
            v0.y = acc[mi][ni][1] * W_INV + bb.y;
            v1.x = acc[mi][ni][2] * W_INV + bb.x;
            v1.y = acc[mi][ni][3] * W_INV + bb.y;
            *reinterpret_cast<float2*>(out + (size_t)row0 * DN + col) = v0;
            *reinterpret_cast<float2*>(out + (size_t)(row0 + 8) * DN + col) = v1;
        }
    }
}

// ------------------------------ launch -------------------------------------

extern "C" void kernel_launch(void* const* d_in, const int* in_sizes, int n_in,
                              void* d_out, int out_size) {
    (void)in_sizes; (void)n_in; (void)out_size;
    const float* inp  = (const float*)d_in[0];
    const float* w    = (const float*)d_in[1];
    const float* bias = (const float*)d_in[2];
    const int*   mask = (const int*)d_in[3];
    float* out = (float*)d_out;

    static bool attr_set = false;
    if (!attr_set) {
        cudaFuncSetAttribute(gemm_f16, cudaFuncAttributeMaxDynamicSharedMemorySize, SMEM_BYTES);
        attr_set = true;
    }

    prep_a_kernel<<<4096, 256>>>((const float4*)inp);
    prep_w_kernel<<<dim3(DK / 32, DN / 32), dim3(32, 8)>>>(w, mask);
    gemm_f16<<<dim3(DN / BN, DB / BM), 256, SMEM_BYTES>>>(bias, out);
}

// round 5
// speedup vs baseline: 1.2468x; 1.0399x over previous
#include <cuda_runtime.h>
#include <cuda_fp16.h>
#include <cstdint>

// ---------------------------------------------------------------------------
// GPe masked GEMM: out[b,u] = sum_i inputs[b,i]*(w[i,u]*mask[u,i]) + bias[u]
// compute_103 (no 'a') -> legacy mma.sync.m16n8k16 fp16/f32acc path.
// R4: BK 32->64 (48 k-iters, halves barrier overhead), 128x256x64 CTA tile,
// warp tile 64x64, 4-stage cp.async ring (192KB smem), ldmatrix.x4 frags.
// ---------------------------------------------------------------------------

#define DB 16384
#define DK 3072
#define DN 3072
#define BM 128
#define BN 256
#define BK 64
#define NKI (DK / BK)          /* 48 */
#define NSTG 4
#define ROWB 128                              /* bytes per smem row (64 fp16) */
#define A_STAGE_BYTES (BM * ROWB)             /* 16384 */
#define B_STAGE_BYTES (BN * ROWB)             /* 32768 */
#define STAGE_BYTES (A_STAGE_BYTES + B_STAGE_BYTES)  /* 49152 */
#define SMEM_BYTES (NSTG * STAGE_BYTES)              /* 196608 */

#define W_SCALE 16384.0f
#define W_INV   (1.0f / 16384.0f)

__device__ __align__(128) __half g_Ah[(size_t)DB * DK];  // fp16 inputs
__device__ __align__(128) __half g_Wh[(size_t)DN * DK];  // fp16 (w*mask*2^14)^T, [N,K]

// ------------------------------- helpers -----------------------------------

__device__ __forceinline__ void cp16(uint32_t d, const void* s) {
    asm volatile("cp.async.cg.shared.global [%0], [%1], 16;" :: "r"(d), "l"(s) : "memory");
}
__device__ __forceinline__ void cp_commit() { asm volatile("cp.async.commit_group;" ::: "memory"); }
template <int N>
__device__ __forceinline__ void cp_wait() { asm volatile("cp.async.wait_group %0;" :: "n"(N) : "memory"); }

__device__ __forceinline__ void ldsm4(uint32_t& r0, uint32_t& r1, uint32_t& r2, uint32_t& r3,
                                      uint32_t addr) {
    asm volatile("ldmatrix.sync.aligned.m8n8.x4.shared.b16 {%0,%1,%2,%3}, [%4];"
                 : "=r"(r0), "=r"(r1), "=r"(r2), "=r"(r3) : "r"(addr));
}

__device__ __forceinline__ void mma_f16(float& d0, float& d1, float& d2, float& d3,
                                        uint32_t a0, uint32_t a1, uint32_t a2, uint32_t a3,
                                        uint32_t b0, uint32_t b1) {
    asm volatile("mma.sync.aligned.m16n8k16.row.col.f32.f16.f16.f32 "
                 "{%0,%1,%2,%3}, {%4,%5,%6,%7}, {%8,%9}, {%0,%1,%2,%3};"
                 : "+f"(d0), "+f"(d1), "+f"(d2), "+f"(d3)
                 : "r"(a0), "r"(a1), "r"(a2), "r"(a3), "r"(b0), "r"(b1));
}

// --------------------------- prep kernels ----------------------------------

__global__ void prep_a_kernel(const float4* __restrict__ in) {
    size_t i = (size_t)blockIdx.x * blockDim.x + threadIdx.x;
    const size_t stride = (size_t)gridDim.x * blockDim.x;
    uint2* o = reinterpret_cast<uint2*>(g_Ah);
    const size_t n4 = (size_t)DB * DK / 4;
    for (; i < n4; i += stride) {
        float4 v = __ldg(in + i);
        __half2 h01 = __floats2half2_rn(v.x, v.y);
        __half2 h23 = __floats2half2_rn(v.z, v.w);
        uint2 u;
        u.x = *reinterpret_cast<uint32_t*>(&h01);
        u.y = *reinterpret_cast<uint32_t*>(&h23);
        o[i] = u;
    }
}

// g_Wh[n][k] = half(w[k][n] * mask[n][k] * 2^14), 32x32 smem transpose tiles.
__global__ void prep_w_kernel(const float* __restrict__ w, const int* __restrict__ mask) {
    __shared__ float t[32][33];
    const int k0 = blockIdx.x * 32, n0 = blockIdx.y * 32;
    const int tx = threadIdx.x, ty = threadIdx.y;   // (32, 8)
#pragma unroll
    for (int j = 0; j < 4; ++j) {
        int k = k0 + ty + 8 * j;
        t[ty + 8 * j][tx] = w[(size_t)k * DN + n0 + tx];
    }
    __syncthreads();
#pragma unroll
    for (int j = 0; j < 4; ++j) {
        int n = n0 + ty + 8 * j;
        int k = k0 + tx;
        float v = t[tx][ty + 8 * j] * (float)mask[(size_t)n * DK + k] * W_SCALE;
        g_Wh[(size_t)n * DK + k] = __float2half_rn(v);
    }
}

// ------------------------------ GEMM ---------------------------------------
// Smem stage: A[128 rows][128B] then B[256 rows][128B]. 16B-chunk xor swizzle
// within a row: chunk' = chunk ^ (row & 7). Conflict-free for cp.async writes
// (8 consecutive threads cover 8 distinct banks of one row) and ldmatrix
// reads (8 consecutive rows -> 8 distinct banks).

__global__ void __launch_bounds__(256, 1) gemm_f16(const float* __restrict__ bias,
                                                   float* __restrict__ out) {
    extern __shared__ char smem[];

    const int tid = threadIdx.x;
    const int wid = tid >> 5;
    const int lane = tid & 31;
    const int gid = lane >> 2;
    const int tg = lane & 3;
    const int warp_m = wid & 1;     // 64-row slice
    const int warp_n = wid >> 1;    // 64-col slice
    const int m0 = blockIdx.y * BM;
    const int n0 = blockIdx.x * BN;

    const uint32_t smemBase = (uint32_t)__cvta_generic_to_shared(smem);

    // ---- cp.async base mapping (linear in chunk-group j) -------------------
    // cid = tid + 256*j ; row = cid>>3 = (tid>>3) + 32*j ; c4 = tid&7.
    // key = row&7 = (tid>>3)&7 (invariant in j). dst_j = dst0 + j*32*ROWB.
    const int r0 = tid >> 3;
    const int c4 = tid & 7;
    const uint32_t key0 = (uint32_t)(r0 & 7);
    const uint32_t dstRow0 = (uint32_t)r0 * ROWB + (((uint32_t)c4 ^ key0) << 4);
    const char* aSrc0 = (const char*)(g_Ah + (size_t)(m0 + r0) * DK + c4 * 8);
    const char* bSrc0 = (const char*)(g_Wh + (size_t)(n0 + r0) * DK + c4 * 8);
    const size_t srcRowStride = (size_t)32 * DK * 2;   // 32 rows down per j

    // ---- ldmatrix row bases ------------------------------------------------
    // A: row = warp_m*64 + mi*16 + (lane&15), chunk base ac0 = lane>>4.
    // B: row = warp_n*64 + nj*16 + ((lane>>4)<<3) + (lane&7), bc0 = (lane>>3)&1.
    const int ac0 = lane >> 4;
    const int arow = warp_m * 64 + (lane & 15);
    const int bc0 = (lane >> 3) & 1;
    const int brow = warp_n * 64 + ((lane >> 4) << 3) + (lane & 7);

    uint32_t aBase[4], aKey[4], bBase[4], bKey[4];
#pragma unroll
    for (int mi = 0; mi < 4; ++mi) {
        int row = arow + mi * 16;
        aBase[mi] = (uint32_t)row * ROWB;
        aKey[mi] = (uint32_t)(row & 7);
    }
#pragma unroll
    for (int nj = 0; nj < 4; ++nj) {
        int row = brow + nj * 16;
        bBase[nj] = A_STAGE_BYTES + (uint32_t)row * ROWB;
        bKey[nj] = (uint32_t)(row & 7);
    }

    float acc[4][8][4];
#pragma unroll
    for (int mi = 0; mi < 4; ++mi)
#pragma unroll
        for (int ni = 0; ni < 8; ++ni)
#pragma unroll
            for (int q = 0; q < 4; ++q) acc[mi][ni][q] = 0.0f;

    // ---- prologue: fill stages 0..2 ----------------------------------------
#pragma unroll
    for (int p = 0; p < NSTG - 1; ++p) {
        uint32_t st = smemBase + p * STAGE_BYTES;
        size_t kofs = (size_t)p * (BK * 2);
#pragma unroll
        for (int j = 0; j < 4; ++j)
            cp16(st + dstRow0 + j * 32 * ROWB, aSrc0 + j * srcRowStride + kofs);
#pragma unroll
        for (int j = 0; j < 8; ++j)
            cp16(st + A_STAGE_BYTES + dstRow0 + j * 32 * ROWB, bSrc0 + j * srcRowStride + kofs);
        cp_commit();
    }

    // ---- mainloop ----------------------------------------------------------
    for (int it = 0; it < NKI; ++it) {
        cp_wait<NSTG - 2>();
        __syncthreads();

        const int nf = it + NSTG - 1;
        if (nf < NKI) {
            uint32_t st = smemBase + (nf & (NSTG - 1)) * STAGE_BYTES;
            size_t kofs = (size_t)nf * (BK * 2);
#pragma unroll
            for (int j = 0; j < 4; ++j)
                cp16(st + dstRow0 + j * 32 * ROWB, aSrc0 + j * srcRowStride + kofs);
#pragma unroll
            for (int j = 0; j < 8; ++j)
                cp16(st + A_STAGE_BYTES + dstRow0 + j * 32 * ROWB, bSrc0 + j * srcRowStride + kofs);
        }
        cp_commit();

        const uint32_t stg = smemBase + (it & (NSTG - 1)) * STAGE_BYTES;
#pragma unroll
        for (int ks = 0; ks < 4; ++ks) {
            uint32_t bf[4][4];
#pragma unroll
            for (int nj = 0; nj < 4; ++nj)
                ldsm4(bf[nj][0], bf[nj][1], bf[nj][2], bf[nj][3],
                      stg + bBase[nj] + ((((uint32_t)(bc0 + 2 * ks)) ^ bKey[nj]) << 4));
#pragma unroll
            for (int mi = 0; mi < 4; ++mi) {
                uint32_t a0, a1, a2, a3;
                ldsm4(a0, a1, a2, a3,
                      stg + aBase[mi] + ((((uint32_t)(ac0 + 2 * ks)) ^ aKey[mi]) << 4));
#pragma unroll
                for (int nj = 0; nj < 4; ++nj) {
                    mma_f16(acc[mi][2 * nj][0], acc[mi][2 * nj][1],
                            acc[mi][2 * nj][2], acc[mi][2 * nj][3],
                            a0, a1, a2, a3, bf[nj][0], bf[nj][1]);
                    mma_f16(acc[mi][2 * nj + 1][0], acc[mi][2 * nj + 1][1],
                            acc[mi][2 * nj + 1][2], acc[mi][2 * nj + 1][3],
                            a0, a1, a2, a3, bf[nj][2], bf[nj][3]);
                }
            }
        }
    }
    cp_wait<0>();

    // ---- epilogue: scale 2^-14 + bias, float2 direct stores ----------------
#pragma unroll
    for (int mi = 0; mi < 4; ++mi) {
        const int row0 = m0 + warp_m * 64 + mi * 16 + gid;
#pragma unroll
        for (int ni = 0; ni < 8; ++ni) {
            const int col = n0 + warp_n * 64 + ni * 8 + 2 * tg;
            const float2 bb = *reinterpret_cast<const float2*>(bias + col);
            float2 v0, v1;
            v0.x = acc[mi][ni][0] * W_INV + bb.x;
            v0.y = acc[mi][ni][1] * W_INV + bb.y;
            v1.x = acc[mi][ni][2] * W_INV + bb.x;
            v1.y = acc[mi][ni][3] * W_INV + bb.y;
            *reinterpret_cast<float2*>(out + (size_t)row0 * DN + col) = v0;
            *reinterpret_cast<float2*>(out + (size_t)(row0 + 8) * DN + col) = v1;
        }
    }
}

// ------------------------------ launch -------------------------------------

extern "C" void kernel_launch(void* const* d_in, const int* in_sizes, int n_in,
                              void* d_out, int out_size) {
    (void)in_sizes; (void)n_in; (void)out_size;
    const float* inp  = (const float*)d_in[0];
    const float* w    = (const float*)d_in[1];
    const float* bias = (const float*)d_in[2];
    const int*   mask = (const int*)d_in[3];
    float* out = (float*)d_out;

    static bool attr_set = false;
    if (!attr_set) {
        cudaFuncSetAttribute(gemm_f16, cudaFuncAttributeMaxDynamicSharedMemorySize, SMEM_BYTES);
        attr_set = true;
    }

    prep_a_kernel<<<4096, 256>>>((const float4*)inp);
    prep_w_kernel<<<dim3(DK / 32, DN / 32), dim3(32, 8)>>>(w, mask);
    gemm_f16<<<dim3(DN / BN, DB / BM), 256, SMEM_BYTES>>>(bias, out);
}